// round 17
// baseline (speedup 1.0000x reference)
#include <cuda_runtime.h>
#include <cuda.h>
#include <cuda_bf16.h>
#include <cstdint>
#include <cstddef>
#include <math.h>

#define BB   4
#define SS   2048
#define EE   512
#define NH   8
#define DFFC 2048
#define NMASK 256
#define LBL_F 16
#define NTOK (BB*SS)
#define NOUTTOK (BB*NMASK)

#define OFF_L1    0
#define OFF_CE    15360
#define OFF_LABEL 35840
#define OFF_H     52224
#define OFF_MASK  4246528

// ------------------------- device scratch -------------------------
__device__ float g_h [NTOK*EE];
__device__ float g_t [NTOK*EE];
__device__ __nv_bfloat16 g_hh[NTOK*EE], g_hl[NTOK*EE];
__device__ __nv_bfloat16 g_qh[NTOK*EE], g_ql[NTOK*EE];
__device__ __nv_bfloat16 g_kh[NTOK*EE], g_kl[NTOK*EE];
__device__ __nv_bfloat16 g_vh[NTOK*EE], g_vl[NTOK*EE];
__device__ __nv_bfloat16 g_oh[NTOK*EE], g_ol[NTOK*EE];
__device__ __nv_bfloat16 g_fh[NTOK*DFFC], g_fl[NTOK*DFFC];
// transposed weight splits: [(layer*N + n)][K], K-major
__device__ __nv_bfloat16 w_qh[4*EE*EE], w_ql[4*EE*EE];
__device__ __nv_bfloat16 w_kh[4*EE*EE], w_kl[4*EE*EE];
__device__ __nv_bfloat16 w_vh[4*EE*EE], w_vl[4*EE*EE];
__device__ __nv_bfloat16 w_oh[4*EE*EE], w_ol[4*EE*EE];
__device__ __nv_bfloat16 w_1h[4*EE*DFFC], w_1l[4*EE*DFFC];
__device__ __nv_bfloat16 w_2h[4*DFFC*EE], w_2l[4*DFFC*EE];
__device__ unsigned char g_ismasked[NTOK];
__device__ unsigned char g_pad[NTOK];
__device__ int g_kvt[BB];

// ------------------------- helpers -------------------------
__device__ __forceinline__ uint32_t smem_u32(const void* p) {
    return (uint32_t)__cvta_generic_to_shared(p);
}
__device__ __forceinline__ void ldsm4(uint32_t& r0, uint32_t& r1, uint32_t& r2, uint32_t& r3, uint32_t a) {
    asm volatile("ldmatrix.sync.aligned.m8n8.x4.shared.b16 {%0,%1,%2,%3},[%4];"
                 : "=r"(r0), "=r"(r1), "=r"(r2), "=r"(r3) : "r"(a));
}
__device__ __forceinline__ void ldsm4t(uint32_t& r0, uint32_t& r1, uint32_t& r2, uint32_t& r3, uint32_t a) {
    asm volatile("ldmatrix.sync.aligned.m8n8.x4.trans.shared.b16 {%0,%1,%2,%3},[%4];"
                 : "=r"(r0), "=r"(r1), "=r"(r2), "=r"(r3) : "r"(a));
}
__device__ __forceinline__ void mma_bf16(float* c, uint32_t a0, uint32_t a1, uint32_t a2, uint32_t a3,
                                         uint32_t b0, uint32_t b1) {
    asm volatile("mma.sync.aligned.m16n8k16.row.col.f32.bf16.bf16.f32 "
                 "{%0,%1,%2,%3},{%4,%5,%6,%7},{%8,%9},{%0,%1,%2,%3};"
                 : "+f"(c[0]), "+f"(c[1]), "+f"(c[2]), "+f"(c[3])
                 : "r"(a0), "r"(a1), "r"(a2), "r"(a3), "r"(b0), "r"(b1));
}
__device__ __forceinline__ void cpasync16(void* dst, const void* src) {
    uint32_t d = smem_u32(dst);
    asm volatile("cp.async.cg.shared.global [%0],[%1],16;\n" :: "r"(d), "l"(src));
}
#define CP_COMMIT asm volatile("cp.async.commit_group;\n" ::)
#define CP_WAIT0  asm volatile("cp.async.wait_group 0;\n" ::)
#define SW128(o) ((o) ^ (((o) >> 3) & 0x70))

__device__ __forceinline__ void split2(float x, float y, uint32_t& hi, uint32_t& lo) {
    __nv_bfloat16 hx = __float2bfloat16(x), hy = __float2bfloat16(y);
    __nv_bfloat162 hv; hv.x = hx; hv.y = hy;
    hi = *(uint32_t*)&hv;
    __nv_bfloat162 lv;
    lv.x = __float2bfloat16(x - __bfloat162float(hx));
    lv.y = __float2bfloat16(y - __bfloat162float(hy));
    lo = *(uint32_t*)&lv;
}
__device__ __forceinline__ void split1(float v, __nv_bfloat16* hi, __nv_bfloat16* lo, size_t off) {
    __nv_bfloat16 h = __float2bfloat16(v);
    hi[off] = h;
    lo[off] = __float2bfloat16(v - __bfloat162float(h));
}

// ------------------------- mbarrier / TMA -------------------------
#define FENCE_ASYNC() asm volatile("fence.proxy.async.shared::cta;" ::: "memory")
#define MBARRIER_INIT(mb, c)  asm volatile("mbarrier.init.shared.b64 [%0], %1;" :: "r"((uint32_t)(mb)), "r"((uint32_t)(c)) : "memory")
#define MBARRIER_EXPECT_TX(mb, tx) asm volatile("mbarrier.arrive.expect_tx.shared.b64 _, [%0], %1;" :: "r"((uint32_t)(mb)), "r"((uint32_t)(tx)) : "memory")
#define MBARRIER_WAIT_PARITY(mb, ph) do { \
    uint32_t _m = (uint32_t)(mb), _p = (uint32_t)(ph), _d; \
    asm volatile("{\n\t.reg .pred p;\n\tmbarrier.try_wait.parity.acquire.cta.shared::cta.b64 p, [%1], %2;\n\tselp.b32 %0, 1, 0, p;\n\t}" : "=r"(_d) : "r"(_m), "r"(_p) : "memory"); \
    if (!_d) { \
        asm volatile("{\n\t.reg .pred P1;\n\tWL_%=:\n\tmbarrier.try_wait.parity.acquire.cta.shared::cta.b64 P1, [%0], %1, 0x989680;\n\t@P1 bra.uni WD_%=;\n\tbra.uni WL_%=;\n\tWD_%=:\n\t}" :: "r"(_m), "r"(_p) : "memory"); \
    } \
} while(0)
__device__ __forceinline__ void tma2d(uint32_t dst, const CUtensorMap* m, int ck, int crow, uint32_t mbar) {
    asm volatile("cp.async.bulk.tensor.2d.shared::cta.global.tile.mbarrier::complete_tx::bytes "
        "[%0], [%1, {%2, %3}], [%4];" :: "r"(dst), "l"(m), "r"(ck), "r"(crow), "r"(mbar) : "memory");
}

// ------------------------- prep kernels -------------------------
__global__ void __launch_bounds__(256) k_prep(const unsigned char* __restrict__ mraw,
                                              float* __restrict__ out_mask) {
    int b = blockIdx.x, tid = threadIdx.x;
    int found = 0;
    for (int i = 2048 + tid; i < 8192; i += 256) found |= (mraw[i] != 0);
    found = __syncthreads_or(found);
    int cnt = 0;
    for (int i = tid; i < SS; i += 256) {
        int gi = b * SS + i;
        int p;
        if (found) p = (mraw[gi] != 0);
        else       p = (((const int*)mraw)[gi] != 0);
        g_pad[gi] = (unsigned char)p;
        out_mask[gi] = p ? 1.0f : 0.0f;
        g_ismasked[gi] = 0;
        cnt += !p;
    }
    __shared__ int red[8];
    int lane = tid & 31, w = tid >> 5;
    #pragma unroll
    for (int o = 16; o; o >>= 1) cnt += __shfl_xor_sync(0xffffffffu, cnt, o);
    if (lane == 0) red[w] = cnt;
    __syncthreads();
    if (tid == 0) {
        int len = 0;
        #pragma unroll
        for (int i = 0; i < 8; i++) len += red[i];
        g_kvt[b] = (len + 63) >> 6;
    }
}

__global__ void k_scatter(const int* __restrict__ mp) {
    int t = blockIdx.x * blockDim.x + threadIdx.x;
    if (t < NOUTTOK) g_ismasked[(t / NMASK) * SS + mp[t]] = 1;
}

__global__ void k_label(const float* __restrict__ x, const int* __restrict__ mp,
                        float* __restrict__ outL) {
    int t = blockIdx.x * blockDim.x + threadIdx.x;
    if (t < NOUTTOK * LBL_F) {
        int row = t / LBL_F, f = t % LBL_F;
        outL[t] = x[(size_t)((row / NMASK) * SS + mp[row]) * LBL_F + f];
    }
}

// transposed weight split
__global__ void __launch_bounds__(256) k_splitallT(
    const float* __restrict__ Wq, const float* __restrict__ Wk,
    const float* __restrict__ Wv, const float* __restrict__ Wo,
    const float* __restrict__ W1, const float* __restrict__ W2)
{
    int bid = blockIdx.x;
    const float* src; __nv_bfloat16 *ho, *lo; int Kd, Ndm, idx;
    if (bid < 4096) {
        int m = bid >> 10; idx = bid & 1023;
        src = (m == 0) ? Wq : (m == 1) ? Wk : (m == 2) ? Wv : Wo;
        ho  = (m == 0) ? w_qh : (m == 1) ? w_kh : (m == 2) ? w_vh : w_oh;
        lo  = (m == 0) ? w_ql : (m == 1) ? w_kl : (m == 2) ? w_vl : w_ol;
        Kd = 512; Ndm = 512;
    } else if (bid < 8192) {
        idx = bid - 4096; src = W1; ho = w_1h; lo = w_1l; Kd = 512; Ndm = 2048;
    } else {
        idx = bid - 8192; src = W2; ho = w_2h; lo = w_2l; Kd = 2048; Ndm = 512;
    }
    int TN = Ndm >> 5, TKN = (Kd >> 5) * TN;
    int layer = idx / TKN, t = idx % TKN;
    int tk = t / TN, tn = t % TN;
    const float* S = src + (size_t)layer * Kd * Ndm;
    __shared__ float tile[32][33];
    int tx = threadIdx.x & 31, ty = threadIdx.x >> 5;
    int k0 = tk * 32, n0 = tn * 32;
    #pragma unroll
    for (int i = 0; i < 4; i++)
        tile[ty + i * 8][tx] = S[(size_t)(k0 + ty + i * 8) * Ndm + n0 + tx];
    __syncthreads();
    #pragma unroll
    for (int i = 0; i < 4; i++) {
        int n = n0 + ty + i * 8;
        float v = tile[tx][ty + i * 8];
        size_t o = ((size_t)layer * Ndm + n) * Kd + k0 + tx;
        __nv_bfloat16 h = __float2bfloat16(v);
        ho[o] = h;
        lo[o] = __float2bfloat16(v - __bfloat162float(h));
    }
}

// ------------------------- embedding + h init -------------------------
__global__ void __launch_bounds__(128) k_inith(const float* __restrict__ x,
                                               const float* __restrict__ et,
                                               const float* __restrict__ pe,
                                               const int* __restrict__ mp) {
    int bs = blockIdx.x;
    int s = bs % SS, b = bs / SS;
    int tid = threadIdx.x;
    const float* xr = x + (size_t)bs * LBL_F;
    bool msk;
    {
        const int* mpb = mp + b * NMASK;
        int lo = 0, hi = NMASK;
        while (lo < hi) {
            int mid = (lo + hi) >> 1;
            if (__ldg(mpb + mid) < s) lo = mid + 1; else hi = mid;
        }
        msk = (lo < NMASK) && (__ldg(mpb + lo) == s);
    }
    int amino = msk ? 0 : (int)xr[15];
    if (amino < 0) amino = 0;
    if (amino > 19) amino = 19;
    const float* er = et + (size_t)amino * 497;
    float mn = 1e30f, mx = -1e30f;
    for (int i = tid; i < 497; i += 128) {
        float v = er[i];
        mn = fminf(mn, v);
        mx = fmaxf(mx, v);
    }
    #pragma unroll
    for (int o = 16; o; o >>= 1) {
        mn = fminf(mn, __shfl_xor_sync(0xffffffffu, mn, o));
        mx = fmaxf(mx, __shfl_xor_sync(0xffffffffu, mx, o));
    }
    __shared__ float smn[4], smx[4];
    int w = tid >> 5, lane = tid & 31;
    if (lane == 0) { smn[w] = mn; smx[w] = mx; }
    __syncthreads();
    mn = fminf(fminf(smn[0], smn[1]), fminf(smn[2], smn[3]));
    mx = fmaxf(fmaxf(smx[0], smx[1]), fmaxf(smx[2], smx[3]));
    float inv = 1.0f / (mx - mn);
    float* hr = g_h + (size_t)bs * EE;
    const float* per = pe + (size_t)s * EE;
    for (int e = tid; e < EE; e += 128) {
        float val = (e < 15) ? (msk ? 0.0f : xr[e]) : (er[e - 15] - mn) * inv;
        float y = val + per[e];
        hr[e] = y;
        split1(y, g_hh, g_hl, (size_t)bs * EE + e);
    }
}

// ------------------------- TMA-fed bf16x3 mma.sync GEMM -------------------------
// C[8192,Nd] = A[8192,Kd] x W[Kd,Nd]; block 128x128, K-chunk 64, 2 stages.
// Stage: Ah|Al|Bh|Bl each 128 rows x 64 bf16 (128B rows, SW128) = 16KB -> 64KB/stage.
#define M_TB 16384
#define M_STAGE (4*M_TB)               // 65536
#define M_SMEM  (2*M_STAGE + 1024)     // 132096 (extra for 1024-alignment of TMA dst)

__global__ void __launch_bounds__(256) k_bgemm_tma(
    const __grid_constant__ CUtensorMap mAh, const __grid_constant__ CUtensorMap mAl,
    const __grid_constant__ CUtensorMap mBh, const __grid_constant__ CUtensorMap mBl,
    const float* __restrict__ bias,
    float* __restrict__ Cf, __nv_bfloat16* __restrict__ Ch, __nv_bfloat16* __restrict__ Cl,
    int Nd, int Kd, int relu, int wrow0)
{
    extern __shared__ char smraw[];
    char* smA = (char*)(((uintptr_t)smraw + 1023) & ~(uintptr_t)1023);   // TMA needs >=128B align
    __shared__ uint64_t mbars[2];
    int tid = threadIdx.x, lane = tid & 31, wid = tid >> 5;
    int wm = (wid & 1) * 64, wn = (wid >> 1) * 32;
    int row0 = blockIdx.y * 128, col0 = blockIdx.x * 128;
    int NC = Kd >> 6;
    uint32_t sb = smem_u32(smA);
    int brow = wrow0 + col0;

    if (tid == 0) {
        MBARRIER_INIT(smem_u32(&mbars[0]), 1);
        MBARRIER_INIT(smem_u32(&mbars[1]), 1);
        FENCE_ASYNC();                 // order generic-proxy init before async-proxy TMA
        #pragma unroll
        for (int c = 0; c < 2; c++) {
            uint32_t st = sb + c * M_STAGE;
            uint32_t mb = smem_u32(&mbars[c]);
            MBARRIER_EXPECT_TX(mb, M_STAGE);
            tma2d(st,            &mAh, c * 64, row0, mb);
            tma2d(st + M_TB,     &mAl, c * 64, row0, mb);
            tma2d(st + 2 * M_TB, &mBh, c * 64, brow, mb);
            tma2d(st + 3 * M_TB, &mBl, c * 64, brow, mb);
        }
    }
    __syncthreads();

    float acc[4][4][4];
    #pragma unroll
    for (int i = 0; i < 4; i++)
        #pragma unroll
        for (int j = 0; j < 4; j++)
            #pragma unroll
            for (int c = 0; c < 4; c++) acc[i][j][c] = 0.0f;

    int lrow = lane & 15, lcol = (lane >> 4) * 16;

    for (int it = 0; it < NC; it++) {
        int s = it & 1, ph = (it >> 1) & 1;
        MBARRIER_WAIT_PARITY(smem_u32(&mbars[s]), ph);

        uint32_t st = sb + s * M_STAGE;
        uint32_t Ah_u = st, Al_u = st + M_TB, Bh_u = st + 2 * M_TB, Bl_u = st + 3 * M_TB;

        #pragma unroll
        for (int ks = 0; ks < 4; ks++) {
            uint32_t kb = ks * 32 + lcol;
            uint32_t offb0 = (uint32_t)((wn + lrow) << 7) + kb;
            uint32_t offb1 = (uint32_t)((wn + 16 + lrow) << 7) + kb;
            uint32_t b0, b1, b2, b3, c0, c1, c2, c3;
            uint32_t d0, d1, d2, d3, e0, e1, e2, e3;
            ldsm4(b0, b1, b2, b3, Bh_u + SW128(offb0));
            ldsm4(c0, c1, c2, c3, Bl_u + SW128(offb0));
            ldsm4(d0, d1, d2, d3, Bh_u + SW128(offb1));
            ldsm4(e0, e1, e2, e3, Bl_u + SW128(offb1));

            #pragma unroll
            for (int mf = 0; mf < 4; mf++) {
                uint32_t offa = (uint32_t)((wm + mf * 16 + lrow) << 7) + kb;
                uint32_t ah0, ah1, ah2, ah3, al0, al1, al2, al3;
                ldsm4(ah0, ah1, ah2, ah3, Ah_u + SW128(offa));
                ldsm4(al0, al1, al2, al3, Al_u + SW128(offa));
                mma_bf16(acc[mf][0], ah0, ah1, ah2, ah3, b0, b2);
                mma_bf16(acc[mf][0], ah0, ah1, ah2, ah3, c0, c2);
                mma_bf16(acc[mf][0], al0, al1, al2, al3, b0, b2);
                mma_bf16(acc[mf][1], ah0, ah1, ah2, ah3, b1, b3);
                mma_bf16(acc[mf][1], ah0, ah1, ah2, ah3, c1, c3);
                mma_bf16(acc[mf][1], al0, al1, al2, al3, b1, b3);
                mma_bf16(acc[mf][2], ah0, ah1, ah2, ah3, d0, d2);
                mma_bf16(acc[mf][2], ah0, ah1, ah2, ah3, e0, e2);
                mma_bf16(acc[mf][2], al0, al1, al2, al3, d0, d2);
                mma_bf16(acc[mf][3], ah0, ah1, ah2, ah3, d1, d3);
                mma_bf16(acc[mf][3], ah0, ah1, ah2, ah3, e1, e3);
                mma_bf16(acc[mf][3], al0, al1, al2, al3, d1, d3);
            }
        }
        __syncthreads();
        if (tid == 0 && it + 2 < NC) {
            uint32_t mb = smem_u32(&mbars[s]);
            MBARRIER_EXPECT_TX(mb, M_STAGE);
            int k0 = (it + 2) * 64;
            tma2d(st,            &mAh, k0, row0, mb);
            tma2d(st + M_TB,     &mAl, k0, row0, mb);
            tma2d(st + 2 * M_TB, &mBh, k0, brow, mb);
            tma2d(st + 3 * M_TB, &mBl, k0, brow, mb);
        }
    }

    int gid = lane >> 2, tig = lane & 3;
    #pragma unroll
    for (int mf = 0; mf < 4; mf++) {
        int rowA = row0 + wm + mf * 16 + gid;
        #pragma unroll
        for (int nf = 0; nf < 4; nf++) {
            int colA = col0 + wn + nf * 8 + tig * 2;
            float b0v = bias[colA], b1v = bias[colA + 1];
            float v00 = acc[mf][nf][0] + b0v, v01 = acc[mf][nf][1] + b1v;
            float v10 = acc[mf][nf][2] + b0v, v11 = acc[mf][nf][3] + b1v;
            if (relu) {
                v00 = fmaxf(v00, 0.0f); v01 = fmaxf(v01, 0.0f);
                v10 = fmaxf(v10, 0.0f); v11 = fmaxf(v11, 0.0f);
            }
            size_t o0 = (size_t)rowA * Nd + colA;
            size_t o1 = (size_t)(rowA + 8) * Nd + colA;
            if (Cf) {
                float2 a; a.x = v00; a.y = v01;
                float2 b; b.x = v10; b.y = v11;
                *(float2*)(Cf + o0) = a;
                *(float2*)(Cf + o1) = b;
            }
            if (Ch) {
                uint32_t hi, lo;
                split2(v00, v01, hi, lo);
                *(uint32_t*)(Ch + o0) = hi; *(uint32_t*)(Cl + o0) = lo;
                split2(v10, v11, hi, lo);
                *(uint32_t*)(Ch + o1) = hi; *(uint32_t*)(Cl + o1) = lo;
            }
        }
    }
}

// ------------------------- tensor-core flash attention (unchanged baseline) -------------------------
#define A_STR 72
#define A_QBY (128*A_STR*2)
#define A_KVM (64*A_STR*2)
#define A_KVST (4*A_KVM)
#define A_SMEM (2*A_QBY + 2*A_KVST)

__global__ void __launch_bounds__(256, 2) k_attn2(
    const __nv_bfloat16* __restrict__ qh, const __nv_bfloat16* __restrict__ ql,
    const __nv_bfloat16* __restrict__ kh, const __nv_bfloat16* __restrict__ kl,
    const __nv_bfloat16* __restrict__ vh, const __nv_bfloat16* __restrict__ vl,
    __nv_bfloat16* __restrict__ oh, __nv_bfloat16* __restrict__ ol,
    const float* __restrict__ a1, const float* __restrict__ a2, int layer)
{
    extern __shared__ char sm[];
    __shared__ float f_s[2][64];
    int tid = threadIdx.x, lane = tid & 31, wid = tid >> 5;
    int bhid = blockIdx.x;
    int b = bhid >> 3, head = bhid & 7;
    int q0 = blockIdx.y * 128;
    float fill = (layer == 0) ? *a1 : ((layer == 1) ? *a2 : 1.0f);
    size_t tokbase = (size_t)b * SS;
    size_t hoff = head * 64;
    int KT = g_kvt[b];

    char* Qh_s = sm;
    char* Ql_s = sm + A_QBY;
    char* kvbase = sm + 2 * A_QBY;

    #pragma unroll
    for (int i = 0; i < 8; i++) {
        int c = tid + i * 256;
        int mat = c >> 10, idx = c & 1023;
        int r = idx >> 3, cq = (idx & 7) * 8;
        const __nv_bfloat16* src = (mat ? ql : qh) + (tokbase + q0 + r) * EE + hoff + cq;
        char* dst = (mat ? Ql_s : Qh_s) + (r * A_STR + cq) * 2;
        cpasync16(dst, src);
    }
    auto kvload = [&](int kt, int st) {
        char* bs = kvbase + st * A_KVST;
        #pragma unroll
        for (int i = 0; i < 8; i++) {
            int c = tid + i * 256;
            int mat = c >> 9, idx = c & 511;
            int r = idx >> 3, cq = (idx & 7) * 8;
            const __nv_bfloat16* srcm = (mat == 0) ? kh : (mat == 1) ? kl : (mat == 2) ? vh : vl;
            cpasync16(bs + mat * A_KVM + (r * A_STR + cq) * 2,
                      srcm + (tokbase + kt * 64 + r) * EE + hoff + cq);
        }
        CP_COMMIT;
    };
    kvload(0, 0);

    float m0 = -1e30f, m1 = -1e30f, l0 = 0.0f, l1 = 0.0f;
    float Oa[8][4];
    #pragma unroll
    for (int i = 0; i < 8; i++)
        #pragma unroll
        for (int j = 0; j < 4; j++) Oa[i][j] = 0.0f;
    uint32_t qfh[4][4], qfl[4][4];
    const float scl = 1.0f / 64.0f;
    int j0 = (lane & 3) * 2;

    for (int kt = 0; kt < KT; kt++) {
        int cur = kt & 1;
        if (tid < 64) {
            int gi = b * SS + kt * 64 + tid;
            f_s[cur][tid] = g_pad[gi] ? 0.0f : (g_ismasked[gi] ? fill : 1.0f);
        }
        CP_WAIT0;
        __syncthreads();
        if (kt + 1 < KT) kvload(kt + 1, cur ^ 1);

        if (kt == 0) {
            uint32_t Qh_u = smem_u32(Qh_s), Ql_u = smem_u32(Ql_s);
            #pragma unroll
            for (int ks = 0; ks < 4; ks++) {
                uint32_t aoff = (uint32_t)(((wid * 16 + (lane & 15)) * A_STR + (lane >> 4) * 8 + ks * 16) * 2);
                ldsm4(qfh[ks][0], qfh[ks][1], qfh[ks][2], qfh[ks][3], Qh_u + aoff);
                ldsm4(qfl[ks][0], qfl[ks][1], qfl[ks][2], qfl[ks][3], Ql_u + aoff);
            }
        }

        char* bs = kvbase + cur * A_KVST;
        uint32_t KHu = smem_u32(bs);
        uint32_t KLu = KHu + A_KVM;
        uint32_t VHu = KHu + 2 * A_KVM;
        uint32_t VLu = KHu + 3 * A_KVM;

        float S[8][4];
        #pragma unroll
        for (int i = 0; i < 8; i++)
            #pragma unroll
            for (int j = 0; j < 4; j++) S[i][j] = 0.0f;

        #pragma unroll
        for (int nf2 = 0; nf2 < 4; nf2++) {
            #pragma unroll
            for (int ks = 0; ks < 4; ks++) {
                uint32_t boff = (uint32_t)(((nf2 * 16 + (lane & 15)) * A_STR + (lane >> 4) * 8 + ks * 16) * 2);
                uint32_t k0r, k1r, k2r, k3r, l0r, l1r, l2r, l3r;
                ldsm4(k0r, k1r, k2r, k3r, KHu + boff);
                ldsm4(l0r, l1r, l2r, l3r, KLu + boff);
                mma_bf16(S[2 * nf2], qfh[ks][0], qfh[ks][1], qfh[ks][2], qfh[ks][3], k0r, k2r);
                mma_bf16(S[2 * nf2], qfh[ks][0], qfh[ks][1], qfh[ks][2], qfh[ks][3], l0r, l2r);
                mma_bf16(S[2 * nf2], qfl[ks][0], qfl[ks][1], qfl[ks][2], qfl[ks][3], k0r, k2r);
                mma_bf16(S[2 * nf2 + 1], qfh[ks][0], qfh[ks][1], qfh[ks][2], qfh[ks][3], k1r, k3r);
                mma_bf16(S[2 * nf2 + 1], qfh[ks][0], qfh[ks][1], qfh[ks][2], qfh[ks][3], l1r, l3r);
                mma_bf16(S[2 * nf2 + 1], qfl[ks][0], qfl[ks][1], qfl[ks][2], qfl[ks][3], k1r, k3r);
            }
        }

        float tm0 = -1e30f, tm1 = -1e30f;
        #pragma unroll
        for (int nf = 0; nf < 8; nf++) {
            float f0 = f_s[cur][nf * 8 + j0], f1 = f_s[cur][nf * 8 + j0 + 1];
            float s00 = (f0 == 0.0f) ? -1e30f : S[nf][0] * f0 * scl;
            float s01 = (f1 == 0.0f) ? -1e30f : S[nf][1] * f1 * scl;
            float s10 = (f0 == 0.0f) ? -1e30f : S[nf][2] * f0 * scl;
            float s11 = (f1 == 0.0f) ? -1e30f : S[nf][3] * f1 * scl;
            S[nf][0] = s00; S[nf][1] = s01; S[nf][2] = s10; S[nf][3] = s11;
            tm0 = fmaxf(tm0, fmaxf(s00, s01));
            tm1 = fmaxf(tm1, fmaxf(s10, s11));
        }
        tm0 = fmaxf(tm0, __shfl_xor_sync(0xffffffffu, tm0, 1));
        tm0 = fmaxf(tm0, __shfl_xor_sync(0xffffffffu, tm0, 2));
        tm1 = fmaxf(tm1, __shfl_xor_sync(0xffffffffu, tm1, 1));
        tm1 = fmaxf(tm1, __shfl_xor_sync(0xffffffffu, tm1, 2));

        float mn0 = fmaxf(m0, tm0), mn1 = fmaxf(m1, tm1);
        float al0 = __expf(m0 - mn0), al1 = __expf(m1 - mn1);
        m0 = mn0; m1 = mn1;

        float rs0 = 0.0f, rs1 = 0.0f;
        uint32_t pH[8][2], pL[8][2];
        #pragma unroll
        for (int nf = 0; nf < 8; nf++) {
            float p00 = (S[nf][0] < -1e29f) ? 0.0f : __expf(S[nf][0] - mn0);
            float p01 = (S[nf][1] < -1e29f) ? 0.0f : __expf(S[nf][1] - mn0);
            float p10 = (S[nf][2] < -1e29f) ? 0.0f : __expf(S[nf][2] - mn1);
            float p11 = (S[nf][3] < -1e29f) ? 0.0f : __expf(S[nf][3] - mn1);
            rs0 += p00 + p01; rs1 += p10 + p11;
            split2(p00, p01, pH[nf][0], pL[nf][0]);
            split2(p10, p11, pH[nf][1], pL[nf][1]);
        }
        rs0 += __shfl_xor_sync(0xffffffffu, rs0, 1);
        rs0 += __shfl_xor_sync(0xffffffffu, rs0, 2);
        rs1 += __shfl_xor_sync(0xffffffffu, rs1, 1);
        rs1 += __shfl_xor_sync(0xffffffffu, rs1, 2);
        l0 = l0 * al0 + rs0;
        l1 = l1 * al1 + rs1;
        #pragma unroll
        for (int nf = 0; nf < 8; nf++) {
            Oa[nf][0] *= al0; Oa[nf][1] *= al0;
            Oa[nf][2] *= al1; Oa[nf][3] *= al1;
        }

        #pragma unroll
        for (int ks = 0; ks < 4; ks++) {
            uint32_t aH0 = pH[2 * ks][0], aH1 = pH[2 * ks][1], aH2 = pH[2 * ks + 1][0], aH3 = pH[2 * ks + 1][1];
            uint32_t aL0 = pL[2 * ks][0], aL1 = pL[2 * ks][1], aL2 = pL[2 * ks + 1][0], aL3 = pL[2 * ks + 1][1];
            #pragma unroll
            for (int g = 0; g < 4; g++) {
                uint32_t voff = (uint32_t)(((ks * 16 + (lane & 15)) * A_STR + g * 16 + (lane >> 4) * 8) * 2);
                uint32_t v0, v1, v2, v3, w0, w1, w2, w3;
                ldsm4t(v0, v1, v2, v3, VHu + voff);
                ldsm4t(w0, w1, w2, w3, VLu + voff);
                mma_bf16(Oa[2 * g], aH0, aH1, aH2, aH3, v0, v1);
                mma_bf16(Oa[2 * g], aH0, aH1, aH2, aH3, w0, w1);
                mma_bf16(Oa[2 * g], aL0, aL1, aL2, aL3, v0, v1);
                mma_bf16(Oa[2 * g + 1], aH0, aH1, aH2, aH3, v2, v3);
                mma_bf16(Oa[2 * g + 1], aH0, aH1, aH2, aH3, w2, w3);
                mma_bf16(Oa[2 * g + 1], aL0, aL1, aL2, aL3, v2, v3);
            }
        }
    }

    float i0 = 1.0f / l0, i1 = 1.0f / l1;
    int r0g = q0 + wid * 16 + (lane >> 2);
    int r1g = r0g + 8;
    size_t obase = (size_t)(b * NH + head) * SS;
    #pragma unroll
    for (int nf = 0; nf < 8; nf++) {
        int d = nf * 8 + j0;
        uint32_t hi, lo;
        split2(Oa[nf][0] * i0, Oa[nf][1] * i0, hi, lo);
        size_t off = (obase + r0g) * 64 + d;
        *(uint32_t*)(oh + off) = hi; *(uint32_t*)(ol + off) = lo;
        split2(Oa[nf][2] * i1, Oa[nf][3] * i1, hi, lo);
        off = (obase + r1g) * 64 + d;
        *(uint32_t*)(oh + off) = hi; *(uint32_t*)(ol + off) = lo;
    }
}

// ------------------------- residual + LayerNorm -------------------------
__device__ __forceinline__ float blk_sum256(float v) {
    __shared__ float red[8];
    int lane = threadIdx.x & 31, w = threadIdx.x >> 5;
    #pragma unroll
    for (int o = 16; o; o >>= 1) v += __shfl_xor_sync(0xffffffffu, v, o);
    if (lane == 0) red[w] = v;
    __syncthreads();
    float t = (lane < 8) ? red[lane] : 0.0f;
    #pragma unroll
    for (int o = 16; o; o >>= 1) t += __shfl_xor_sync(0xffffffffu, t, o);
    __syncthreads();
    return t;
}

__global__ void __launch_bounds__(256) k_addln(float* __restrict__ h,
                                               const float* __restrict__ res,
                                               const float* __restrict__ gs,
                                               const float* __restrict__ gb) {
    int row = blockIdx.x;
    int tid = threadIdx.x;
    float* hr = h + (size_t)row * EE;
    const float* rr = res + (size_t)row * EE;
    float2 xa = *(const float2*)(hr + 2 * tid);
    float2 xb = *(const float2*)(rr + 2 * tid);
    float x0 = xa.x + xb.x, x1 = xa.y + xb.y;
    float mu = blk_sum256(x0 + x1) * (1.0f / 512.0f);
    float d0 = x0 - mu, d1 = x1 - mu;
    float var = blk_sum256(d0 * d0 + d1 * d1) * (1.0f / 512.0f);
    float inv = rsqrtf(var + 1e-5f);
    float2 gsv = *(const float2*)(gs + 2 * tid);
    float2 gbv = *(const float2*)(gb + 2 * tid);
    float y0 = d0 * inv * gsv.x + gbv.x;
    float y1 = d1 * inv * gsv.y + gbv.y;
    float2 yo; yo.x = y0; yo.y = y1;
    *(float2*)(hr + 2 * tid) = yo;
    uint32_t hi, lo;
    split2(y0, y1, hi, lo);
    *(uint32_t*)(g_hh + (size_t)row * EE + 2 * tid) = hi;
    *(uint32_t*)(g_hl + (size_t)row * EE + 2 * tid) = lo;
}

// ------------------------- final FC + h copy -------------------------
__global__ void __launch_bounds__(64) k_finalfc(const float* __restrict__ h,
                                                const int* __restrict__ mp,
                                                const float* __restrict__ fcw,
                                                const float* __restrict__ fcb,
                                                float* __restrict__ out) {
    int row = blockIdx.x;
    int b = row / NMASK;
    int sp = mp[row];
    __shared__ float hrow[EE];
    const float* hr = h + (size_t)(b * SS + sp) * EE;
    for (int i = threadIdx.x; i < EE; i += 64) hrow[i] = hr[i];
    __syncthreads();
    for (int j = threadIdx.x; j < 35; j += 64) {
        float acc = fcb[j];
        for (int kk = 0; kk < EE; kk++) acc += hrow[kk] * fcw[kk * 35 + j];
        if (j < 15) out[OFF_L1 + row * 15 + j] = acc;
        else        out[OFF_CE + row * 20 + (j - 15)] = acc;
    }
}

__global__ void k_copyh(float* __restrict__ dst) {
    size_t i = ((size_t)blockIdx.x * blockDim.x + threadIdx.x) * 4;
    if (i < (size_t)NTOK * EE) *(float4*)(dst + i) = *(const float4*)(g_h + i);
}

// ------------------------- host: tensormap encode -------------------------
typedef CUresult (*PFN_tmapenc)(CUtensorMap*, CUtensorMapDataType, cuuint32_t, void*,
    const cuuint64_t*, const cuuint64_t*, const cuuint32_t*, const cuuint32_t*,
    CUtensorMapInterleave, CUtensorMapSwizzle, CUtensorMapL2promotion, CUtensorMapFloatOOBfill);

static void enc_map(PFN_tmapenc fn, CUtensorMap* m, void* ptr, uint64_t Kd, uint64_t rows) {
    cuuint64_t dims[2] = {Kd, rows};
    cuuint64_t strides[1] = {Kd * 2};
    cuuint32_t box[2] = {64, 128};
    cuuint32_t es[2] = {1, 1};
    fn(m, CU_TENSOR_MAP_DATA_TYPE_BFLOAT16, 2, ptr, dims, strides, box, es,
       CU_TENSOR_MAP_INTERLEAVE_NONE, CU_TENSOR_MAP_SWIZZLE_128B,
       CU_TENSOR_MAP_L2_PROMOTION_L2_128B, CU_TENSOR_MAP_FLOAT_OOB_FILL_NONE);
}

extern "C" void kernel_launch(void* const* d_in, const int* in_sizes, int n_in,
                              void* d_out, int out_size) {
    const float* x    = (const float*)d_in[0];
    const void*  mraw = d_in[1];
    const int*   mp   = (const int*)d_in[2];
    const float* a1   = (const float*)d_in[3];
    const float* a2   = (const float*)d_in[4];
    const float* et   = (const float*)d_in[5];
    const float* pe   = (const float*)d_in[6];
    const float* Wq   = (const float*)d_in[7];
    const float* bq   = (const float*)d_in[8];
    const float* Wk   = (const float*)d_in[9];
    const float* bk   = (const float*)d_in[10];
    const float* Wv   = (const float*)d_in[11];
    const float* bv   = (const float*)d_in[12];
    const float* Wo   = (const float*)d_in[13];
    const float* bo   = (const float*)d_in[14];
    const float* l1s  = (const float*)d_in[15];
    const float* l1b  = (const float*)d_in[16];
    const float* W1   = (const float*)d_in[17];
    const float* b1   = (const float*)d_in[18];
    const float* W2   = (const float*)d_in[19];
    const float* b2   = (const float*)d_in[20];
    const float* l2s  = (const float*)d_in[21];
    const float* l2b  = (const float*)d_in[22];
    const float* fcw  = (const float*)d_in[23];
    const float* fcb  = (const float*)d_in[24];
    float* out = (float*)d_out;

    cudaFuncSetAttribute(k_bgemm_tma, cudaFuncAttributeMaxDynamicSharedMemorySize, M_SMEM);
    cudaFuncSetAttribute(k_attn2, cudaFuncAttributeMaxDynamicSharedMemorySize, A_SMEM);

    float *ph, *pt;
    cudaGetSymbolAddress((void**)&ph, g_h);
    cudaGetSymbolAddress((void**)&pt, g_t);
    __nv_bfloat16 *phh, *phl, *pqh, *pql, *pkh, *pkl, *pvh, *pvl, *poh, *pol, *pfh, *pfl;
    cudaGetSymbolAddress((void**)&phh, g_hh); cudaGetSymbolAddress((void**)&phl, g_hl);
    cudaGetSymbolAddress((void**)&pqh, g_qh); cudaGetSymbolAddress((void**)&pql, g_ql);
    cudaGetSymbolAddress((void**)&pkh, g_kh); cudaGetSymbolAddress((void**)&pkl, g_kl);
    cudaGetSymbolAddress((void**)&pvh, g_vh); cudaGetSymbolAddress((void**)&pvl, g_vl);
    cudaGetSymbolAddress((void**)&poh, g_oh); cudaGetSymbolAddress((void**)&pol, g_ol);
    cudaGetSymbolAddress((void**)&pfh, g_fh); cudaGetSymbolAddress((void**)&pfl, g_fl);
    void *wqh, *wql, *wkh, *wkl, *wvh, *wvl, *woh, *wol, *w1h, *w1l, *w2h, *w2l;
    cudaGetSymbolAddress(&wqh, w_qh); cudaGetSymbolAddress(&wql, w_ql);
    cudaGetSymbolAddress(&wkh, w_kh); cudaGetSymbolAddress(&wkl, w_kl);
    cudaGetSymbolAddress(&wvh, w_vh); cudaGetSymbolAddress(&wvl, w_vl);
    cudaGetSymbolAddress(&woh, w_oh); cudaGetSymbolAddress(&wol, w_ol);
    cudaGetSymbolAddress(&w1h, w_1h); cudaGetSymbolAddress(&w1l, w_1l);
    cudaGetSymbolAddress(&w2h, w_2h); cudaGetSymbolAddress(&w2l, w_2l);

    PFN_tmapenc enc = nullptr;
    cudaDriverEntryPointQueryResult qst;
    cudaGetDriverEntryPoint("cuTensorMapEncodeTiled", (void**)&enc, cudaEnableDefault, &qst);

    CUtensorMap mHh, mHl, mOh, mOl, mFh, mFl;
    enc_map(enc, &mHh, phh, 512, 8192);  enc_map(enc, &mHl, phl, 512, 8192);
    enc_map(enc, &mOh, poh, 512, 8192);  enc_map(enc, &mOl, pol, 512, 8192);
    enc_map(enc, &mFh, pfh, 2048, 8192); enc_map(enc, &mFl, pfl, 2048, 8192);
    CUtensorMap mWq[2], mWk[2], mWv[2], mWo[2], mW1[2], mW2[2];
    enc_map(enc, &mWq[0], wqh, 512, 2048);  enc_map(enc, &mWq[1], wql, 512, 2048);
    enc_map(enc, &mWk[0], wkh, 512, 2048);  enc_map(enc, &mWk[1], wkl, 512, 2048);
    enc_map(enc, &mWv[0], wvh, 512, 2048);  enc_map(enc, &mWv[1], wvl, 512, 2048);
    enc_map(enc, &mWo[0], woh, 512, 2048);  enc_map(enc, &mWo[1], wol, 512, 2048);
    enc_map(enc, &mW1[0], w1h, 512, 8192);  enc_map(enc, &mW1[1], w1l, 512, 8192);
    enc_map(enc, &mW2[0], w2h, 2048, 2048); enc_map(enc, &mW2[1], w2l, 2048, 2048);

    dim3 gP(4, 64);      // 512-out GEMMs: (512/128, 8192/128)
    dim3 gF1(16, 64);    // FF1
    dim3 gatt(BB * NH, SS / 128);

    k_splitallT<<<12288, 256>>>(Wq, Wk, Wv, Wo, W1, W2);                  // 0
    k_prep<<<BB, 256>>>((const unsigned char*)mraw, out + OFF_MASK);      // 1
    k_inith<<<NTOK, 128>>>(x, et, pe, mp);                                // 2

    for (int i = 0; i < 4; i++) {
        k_bgemm_tma<<<gP, 256, M_SMEM>>>(mHh, mHl, mWq[0], mWq[1], bq + i * EE,
                                         nullptr, pqh, pql, EE, EE, 0, i * EE);  // i==0: launch 3
        if (i == 0) {
            k_scatter<<<(NOUTTOK + 255) / 256, 256>>>(mp);
            k_label<<<(NOUTTOK * LBL_F + 255) / 256, 256>>>(x, mp, out + OFF_LABEL);
        }
        k_bgemm_tma<<<gP, 256, M_SMEM>>>(mHh, mHl, mWk[0], mWk[1], bk + i * EE,
                                         nullptr, pkh, pkl, EE, EE, 0, i * EE);
        k_bgemm_tma<<<gP, 256, M_SMEM>>>(mHh, mHl, mWv[0], mWv[1], bv + i * EE,
                                         nullptr, pvh, pvl, EE, EE, 0, i * EE);
        k_attn2<<<gatt, 256, A_SMEM>>>(pqh, pql, pkh, pkl, pvh, pvl, poh, pol, a1, a2, i);
        k_bgemm_tma<<<gP, 256, M_SMEM>>>(mOh, mOl, mWo[0], mWo[1], bo + i * EE,
                                         pt, nullptr, nullptr, EE, EE, 0, i * EE);
        k_addln<<<NTOK, 256>>>(ph, pt, l1s + i * EE, l1b + i * EE);
        k_bgemm_tma<<<gF1, 256, M_SMEM>>>(mHh, mHl, mW1[0], mW1[1], b1 + i * DFFC,
                                          nullptr, pfh, pfl, DFFC, EE, 1, i * DFFC);
        k_bgemm_tma<<<gP, 256, M_SMEM>>>(mFh, mFl, mW2[0], mW2[1], b2 + i * EE,
                                         pt, nullptr, nullptr, EE, DFFC, 0, i * EE);
        k_addln<<<NTOK, 256>>>(ph, pt, l2s + i * EE, l2b + i * EE);
    }

    k_finalfc<<<NOUTTOK, 64>>>(ph, mp, fcw, fcb, out);
    k_copyh<<<(NTOK * EE / 4 + 255) / 256, 256>>>(out + OFF_H);
}